// round 15
// baseline (speedup 1.0000x reference)
#include <cuda_runtime.h>
#include <cuda_fp16.h>
#include <cuda.h>
#include <math.h>
#include <stdint.h>

// ---------------- problem constants ----------------
#define T_STEPS 20
#define B_DIM   16384
#define P_DIM   256
#define H_DIM   512
#define S_DIM   512
#define C_DIM   128
#define SC_DIM  640
#define KCAT    1152
#define TAUF    0.25f
#define OMTF    0.75f

// ---------------- GEMM tile config ----------------
#define BM 128
#define BN 128
#define BK 64
#define NSTAGE 3
#define A_BYTES (BM * BK * 2)
#define B_BYTES (BN * BK * 2)
#define STAGE_BYTES (A_BYTES + B_BYTES)
#define SMEM_TOTAL (2048 + NSTAGE * STAGE_BYTES)   // 100352
#define OFF_FULL(s)  ((s) * 8)

// gemm_x2: A fully resident (4 chunks, 64KB) + 2-stage TMA B ring
#define SMEMX2_TOTAL (2048 + 4 * A_BYTES + 2 * B_BYTES)   // 100352

// recurrent persistent kernel
#define R_TILES_M   (B_DIM / BM)      // 128
#define R_TILES_N   (SC_DIM / BN)     // 5
#define R_TILES     (R_TILES_M * R_TILES_N)          // 640
#define R_TOTAL     (T_STEPS * R_TILES)              // 12800
#define R_GRID      296

// ---------------- device scratch ----------------
__device__ __align__(256) __half g_zbuf[(size_t)T_STEPS * B_DIM * H_DIM];
__device__ __align__(256) __half g_act0[(size_t)B_DIM * SC_DIM];
__device__ __align__(256) __half g_act1[(size_t)B_DIM * SC_DIM];
__device__ __align__(256) float  g_in  [(size_t)B_DIM * SC_DIM];
__device__ __align__(256) __half g_wphT  [H_DIM * P_DIM];
__device__ __align__(256) __half g_wcombT[SC_DIM * KCAT];
__device__ unsigned g_ready[T_STEPS * R_TILES_M];
__device__ unsigned g_counter;

// ---------------- PTX helpers ----------------
__device__ __forceinline__ uint32_t smem_u32(const void* p) {
    uint32_t a;
    asm("{ .reg .u64 t; cvta.to.shared.u64 t, %1; cvt.u32.u64 %0, t; }" : "=r"(a) : "l"(p));
    return a;
}
__device__ __forceinline__ void mbar_init(uint32_t m, uint32_t cnt) {
    asm volatile("mbarrier.init.shared.b64 [%0], %1;" :: "r"(m), "r"(cnt) : "memory");
}
__device__ __forceinline__ void mbar_expect_tx(uint32_t m, uint32_t bytes) {
    asm volatile("mbarrier.arrive.expect_tx.shared.b64 _, [%0], %1;" :: "r"(m), "r"(bytes) : "memory");
}
__device__ __forceinline__ void mbar_wait(uint32_t m, uint32_t parity) {
    asm volatile(
        "{\n\t.reg .pred P;\n\t"
        "WL_%=:\n\t"
        "mbarrier.try_wait.parity.acquire.cta.shared::cta.b64 P, [%0], %1, 0x989680;\n\t"
        "@P bra.uni WD_%=;\n\t"
        "bra.uni WL_%=;\n\t"
        "WD_%=:\n\t}"
        :: "r"(m), "r"(parity) : "memory");
}
__device__ __forceinline__ void tma2d(uint32_t dst, const CUtensorMap* map, int x, int y, uint32_t mbar) {
    asm volatile(
        "cp.async.bulk.tensor.2d.shared::cta.global.tile.mbarrier::complete_tx::bytes "
        "[%0], [%1, {%2, %3}], [%4];"
        :: "r"(dst), "l"(map), "r"(x), "r"(y), "r"(mbar) : "memory");
}
__device__ __forceinline__ void ldsm4(uint32_t* r, uint32_t addr) {
    asm volatile("ldmatrix.sync.aligned.m8n8.x4.shared.b16 {%0,%1,%2,%3}, [%4];"
                 : "=r"(r[0]), "=r"(r[1]), "=r"(r[2]), "=r"(r[3]) : "r"(addr));
}
__device__ __forceinline__ void mma16816h(uint32_t* c, const uint32_t* a, uint32_t b0, uint32_t b1) {
    asm volatile(
        "mma.sync.aligned.m16n8k16.row.col.f16.f16.f16.f16 "
        "{%0,%1}, {%2,%3,%4,%5}, {%6,%7}, {%0,%1};"
        : "+r"(c[0]), "+r"(c[1])
        : "r"(a[0]), "r"(a[1]), "r"(a[2]), "r"(a[3]), "r"(b0), "r"(b1));
}
__device__ __forceinline__ void cpa16(uint32_t dst, const void* src) {
    asm volatile("cp.async.cg.shared.global [%0], [%1], 16;" :: "r"(dst), "l"(src));
}
__device__ __forceinline__ void cpa_commit() { asm volatile("cp.async.commit_group;" ::: "memory"); }
template<int N> __device__ __forceinline__ void cpa_wait() {
    asm volatile("cp.async.wait_group %0;" :: "n"(N) : "memory");
}
__device__ __forceinline__ void red_release(unsigned* p) {
    asm volatile("red.release.gpu.global.add.u32 [%0], 1;" :: "l"(p) : "memory");
}
__device__ __forceinline__ unsigned ld_acquire(const unsigned* p) {
    unsigned v;
    asm volatile("ld.acquire.gpu.global.u32 %0, [%1];" : "=r"(v) : "l"(p) : "memory");
    return v;
}
__device__ __forceinline__ float sigf(float x) { return 1.0f / (1.0f + __expf(-x)); }

// ============================================================================
// gemm_x2: Z = X(fp32) @ WphT^T, fp16 accum (R12-validated, unchanged)
// ============================================================================
__global__ void __launch_bounds__(256, 2)
gemm_x2(const float* __restrict__ X,
        const __grid_constant__ CUtensorMap tma_b,
        __half* __restrict__ hout)
{
    extern __shared__ char smem[];
    const uint32_t sb = smem_u32(smem);
    const uint32_t stage0 = (sb + 64 + 1023) & ~1023u;
    const uint32_t A0 = stage0;
    const uint32_t B0 = stage0 + 4 * A_BYTES;
    const int tid  = threadIdx.x;
    const int lane = tid & 31;
    const int w    = tid >> 5;
    const int wm   = w & 3;
    const int wn   = w >> 2;
    const int m0 = blockIdx.x * BM;

    if (tid == 0) {
        mbar_init(sb + OFF_FULL(0), 1);
        mbar_init(sb + OFF_FULL(1), 1);
    }
    __syncthreads();
    if (tid == 0) {
        mbar_expect_tx(sb + OFF_FULL(0), B_BYTES);
        tma2d(B0,           &tma_b, 0 * BK, 0, sb + OFF_FULL(0));
        mbar_expect_tx(sb + OFF_FULL(1), B_BYTES);
        tma2d(B0 + B_BYTES, &tma_b, 1 * BK, 0, sb + OFF_FULL(1));
    }

    int rI[8], cI[8];
    uint32_t sOff[8];
    #pragma unroll
    for (int q = 0; q < 8; q++) {
        int i = tid + q * 256;
        int r = i >> 4, c4 = i & 15;
        int c0 = c4 * 4;
        rI[q] = r; cI[q] = c0;
        sOff[q] = (uint32_t)r * 128 + (uint32_t)((((c0 >> 3) ^ (r & 7)) * 16) + (c0 & 7) * 2);
    }
    #pragma unroll
    for (int c = 0; c < 4; c++) {
        float4 xv[8];
        #pragma unroll
        for (int q = 0; q < 8; q++)
            xv[q] = __ldg((const float4*)(X + (size_t)(m0 + rI[q]) * P_DIM + c * BK + cI[q]));
        const uint32_t stA = A0 + c * A_BYTES;
        #pragma unroll
        for (int q = 0; q < 8; q++) {
            uint32_t d = stA + sOff[q];
            __half2 h01 = __floats2half2_rn(xv[q].x, xv[q].y);
            __half2 h23 = __floats2half2_rn(xv[q].z, xv[q].w);
            asm volatile("st.shared.b32 [%0], %1;" :: "r"(d),     "r"(*(uint32_t*)&h01));
            asm volatile("st.shared.b32 [%0], %1;" :: "r"(d + 4), "r"(*(uint32_t*)&h23));
        }
    }
    __syncthreads();

    const uint32_t xr   = (uint32_t)(lane & 7) * 16;
    const uint32_t koff = (uint32_t)(lane >> 4) * 16;
    uint32_t aRow[2], bRow[4];
    #pragma unroll
    for (int mi = 0; mi < 2; mi++)
        aRow[mi] = (uint32_t)(wm * 32 + mi * 16 + (lane & 15)) * 128;
    #pragma unroll
    for (int nq = 0; nq < 4; nq++)
        bRow[nq] = (uint32_t)(wn * 64 + nq * 16 + (lane & 15)) * 128;
    const int rbase = lane >> 2;
    const int cpair = (lane & 3) * 2;

    #pragma unroll 1
    for (int nt = 0; nt < 4; nt++) {
        uint32_t hacc[2][8][2];
        #pragma unroll
        for (int mi = 0; mi < 2; mi++)
            #pragma unroll
            for (int ni = 0; ni < 8; ni++) { hacc[mi][ni][0] = 0u; hacc[mi][ni][1] = 0u; }

        #pragma unroll
        for (int kc = 0; kc < 4; kc++) {
            const int idx = nt * 4 + kc;
            mbar_wait(sb + OFF_FULL(idx & 1), (uint32_t)((idx >> 1) & 1));
            const uint32_t stA = A0 + kc * A_BYTES;
            const uint32_t stB = B0 + (idx & 1) * B_BYTES;
            #pragma unroll
            for (int k16 = 0; k16 < 4; k16++) {
                const uint32_t kb = (uint32_t)k16 * 32 + koff;
                uint32_t af[2][4], bf[4][4];
                #pragma unroll
                for (int mi = 0; mi < 2; mi++)
                    ldsm4(af[mi], stA + aRow[mi] + (kb ^ xr));
                #pragma unroll
                for (int nq = 0; nq < 4; nq++)
                    ldsm4(bf[nq], stB + bRow[nq] + (kb ^ xr));
                #pragma unroll
                for (int mi = 0; mi < 2; mi++)
                    #pragma unroll
                    for (int nq = 0; nq < 4; nq++) {
                        mma16816h(hacc[mi][nq * 2 + 0], af[mi], bf[nq][0], bf[nq][2]);
                        mma16816h(hacc[mi][nq * 2 + 1], af[mi], bf[nq][1], bf[nq][3]);
                    }
            }
            __syncthreads();
            if (tid == 0 && idx + 2 < 16) {
                const int i2 = idx + 2;
                const int nt2 = i2 >> 2, kc2 = i2 & 3;
                mbar_expect_tx(sb + OFF_FULL(i2 & 1), B_BYTES);
                tma2d(B0 + (i2 & 1) * B_BYTES, &tma_b, kc2 * BK, nt2 * BN, sb + OFF_FULL(i2 & 1));
            }
        }

        const int n0 = nt * BN;
        #pragma unroll
        for (int mi = 0; mi < 2; mi++)
            #pragma unroll
            for (int h = 0; h < 2; h++) {
                const int m = m0 + wm * 32 + mi * 16 + rbase + h * 8;
                #pragma unroll
                for (int ni = 0; ni < 8; ni++) {
                    const int n = n0 + wn * 64 + ni * 8 + cpair;
                    *(uint32_t*)(hout + (size_t)m * H_DIM + n) = hacc[mi][ni][h];
                }
            }
    }
}

// ============================================================================
// hps_scan: standalone, fully parallel
// ============================================================================
__global__ void hps_scan(const float* __restrict__ bias_hps) {
    int idx = blockIdx.x * blockDim.x + threadIdx.x;
    if (idx >= B_DIM * H_DIM) return;
    float b = bias_hps[idx % H_DIM];
    float prev = 0.0f;
    #pragma unroll
    for (int t = 0; t < T_STEPS; t++) {
        size_t off = (size_t)t * (B_DIM * H_DIM) + idx;
        float z = __half2float(g_zbuf[off]);
        g_zbuf[off] = __float2half_rn(sigf(prev));
        prev = TAUF * (z + b) + OMTF * prev;
    }
}

// ============================================================================
// rec_persist: K-SPLIT warp layout. 8 warps = (wk,wm,wn) in 2x2x2.
// Each warp: 64x64 output tile, HALF the k16 steps per chunk (wk selects).
// Smem read amplification drops 96KB -> 64KB per chunk (A x2, B x2).
// Partial accumulators merged once per tile via smem; wk=0 does epilogue.
// Mainloop wait/sync structure = R12 (proven).
// ============================================================================
__global__ void __launch_bounds__(256, 2)
rec_persist(const float* __restrict__ bias_s,
            const float* __restrict__ bias_css,
            float* __restrict__ out)
{
    extern __shared__ char smem[];
    unsigned* sg = (unsigned*)smem;
    const uint32_t sb = smem_u32(smem);
    const uint32_t stage0 = (sb + 16 + 1023) & ~1023u;
    const int tid  = threadIdx.x;
    const int lane = tid & 31;
    const int w    = tid >> 5;
    const int wk   = w & 1;          // k-half
    const int wm   = (w >> 1) & 1;   // 64-row half
    const int wn   = (w >> 2) & 1;   // 64-col half
    const int pid  = w >> 1;         // warp-pair id 0..3

    uint32_t dstOff[4];
    int rIdx[4], cIdx[4];
    #pragma unroll
    for (int p = 0; p < 4; p++) {
        int i = tid + p * 256;
        int r = i >> 3, c = i & 7;
        rIdx[p] = r; cIdx[p] = c;
        dstOff[p] = (uint32_t)r * 128 + (uint32_t)((c ^ (r & 7)) * 16);
    }

    const uint32_t xr   = (uint32_t)(lane & 7) * 16;
    const uint32_t koff = (uint32_t)(lane >> 4) * 16;
    uint32_t aRow[4], bRow[4];
    #pragma unroll
    for (int mi = 0; mi < 4; mi++)
        aRow[mi] = (uint32_t)(wm * 64 + mi * 16 + (lane & 15)) * 128;
    #pragma unroll
    for (int nq = 0; nq < 4; nq++)
        bRow[nq] = (uint32_t)(wn * 64 + nq * 16 + (lane & 15)) * 128;

    // merge buffer (reuses stage memory after mainloop): 4 pairs x 8KB
    const uint32_t mbase = stage0 + (uint32_t)pid * 8192 + (uint32_t)lane * 4;

    while (true) {
        if (tid == 0) sg[0] = atomicAdd(&g_counter, 1u);
        __syncthreads();
        const unsigned g = sg[0];
        if (g >= (unsigned)R_TOTAL) break;

        const int t  = (int)(g / R_TILES);
        const int rm = (int)(g % R_TILES);
        const int m  = rm / R_TILES_N;
        const int nn = rm % R_TILES_N;
        const int m0 = m * BM;
        const int n0 = nn * BN;
        const bool css = (n0 >= S_DIM);
        const int nk = css ? (S_DIM / BK) : (KCAT / BK);   // 8 or 18

        if (t > 0) {
            if (tid == 0) {
                while (ld_acquire(&g_ready[(t - 1) * R_TILES_M + m]) < (unsigned)R_TILES_N)
                    __nanosleep(64);
            }
        }
        __syncthreads();

        const __half* Aact = (t & 1) ? g_act1 : g_act0;
        __half*       Aout = (t & 1) ? g_act0 : g_act1;
        const __half* Ahps = g_zbuf + (size_t)t * B_DIM * H_DIM;

        #define A_SRC(kc, p) \
            (((kc) < R_TILES_N * 2) \
             ? (Aact + (size_t)(m0 + rIdx[p]) * SC_DIM + (kc) * BK + cIdx[p] * 8) \
             : (Ahps + (size_t)(m0 + rIdx[p]) * H_DIM + ((kc) - R_TILES_N * 2) * BK + cIdx[p] * 8))
        #define PREFETCH(kc) do { \
            const uint32_t st_ = stage0 + ((kc) % NSTAGE) * STAGE_BYTES; \
            _Pragma("unroll") \
            for (int p = 0; p < 4; p++) \
                cpa16(st_ + dstOff[p], A_SRC((kc), p)); \
            _Pragma("unroll") \
            for (int p = 0; p < 4; p++) \
                cpa16(st_ + A_BYTES + dstOff[p], \
                      g_wcombT + (size_t)(n0 + rIdx[p]) * KCAT + (kc) * BK + cIdx[p] * 8); \
            cpa_commit(); \
        } while (0)

        // R12-style prologue: 3 stages
        PREFETCH(0);
        PREFETCH(1);
        PREFETCH(2);

        uint32_t hacc[4][8][2];
        uint32_t* hf = &hacc[0][0][0];   // 64 regs flat
        #pragma unroll
        for (int i = 0; i < 64; i++) hf[i] = 0u;

        #pragma unroll 1
        for (int kc = 0; kc < nk; kc++) {
            const int rem = nk - 1 - kc;
            if (rem >= 2)      cpa_wait<NSTAGE - 1>();
            else if (rem == 1) cpa_wait<1>();
            else               cpa_wait<0>();
            __syncthreads();

            const uint32_t stA = stage0 + (kc % NSTAGE) * STAGE_BYTES;
            const uint32_t stB = stA + A_BYTES;

            #pragma unroll
            for (int kh = 0; kh < 2; kh++) {
                const int k16 = wk * 2 + kh;
                const uint32_t kb = (uint32_t)k16 * 32 + koff;
                uint32_t af[4][4], bf[4][4];
                #pragma unroll
                for (int mi = 0; mi < 4; mi++)
                    ldsm4(af[mi], stA + aRow[mi] + (kb ^ xr));
                #pragma unroll
                for (int nq = 0; nq < 4; nq++)
                    ldsm4(bf[nq], stB + bRow[nq] + (kb ^ xr));
                #pragma unroll
                for (int mi = 0; mi < 4; mi++)
                    #pragma unroll
                    for (int nq = 0; nq < 4; nq++) {
                        mma16816h(hacc[mi][nq * 2 + 0], af[mi], bf[nq][0], bf[nq][2]);
                        mma16816h(hacc[mi][nq * 2 + 1], af[mi], bf[nq][1], bf[nq][3]);
                    }
            }
            __syncthreads();
            if (kc + NSTAGE < nk) PREFETCH(kc + NSTAGE);
        }
        #undef PREFETCH
        #undef A_SRC

        // ---- merge k-halves: wk=1 dumps, wk=0 adds ----
        __syncthreads();   // stages free; all mma done
        if (wk == 1) {
            #pragma unroll
            for (int i = 0; i < 64; i++)
                asm volatile("st.shared.b32 [%0], %1;" :: "r"(mbase + (uint32_t)i * 128), "r"(hf[i]));
        }
        __syncthreads();

        if (wk == 0) {
            #pragma unroll
            for (int i = 0; i < 64; i++) {
                uint32_t v;
                asm volatile("ld.shared.b32 %0, [%1];" : "=r"(v) : "r"(mbase + (uint32_t)i * 128));
                __half2 s = __hadd2(*(__half2*)&hf[i], *(__half2*)&v);
                hf[i] = *(uint32_t*)&s;
            }

            float* dptr = (t >= T_STEPS - 4)
                          ? out + (size_t)(t - (T_STEPS - 4)) * B_DIM * S_DIM
                          : nullptr;
            const int rbase = lane >> 2;
            const int cpair = (lane & 3) * 2;

            #pragma unroll
            for (int mi = 0; mi < 4; mi++) {
                #pragma unroll
                for (int h = 0; h < 2; h++) {
                    const int mr = m0 + wm * 64 + mi * 16 + rbase + h * 8;
                    #pragma unroll
                    for (int ni = 0; ni < 8; ni++) {
                        const int n = n0 + wn * 64 + ni * 8 + cpair;
                        const float2 c = __half22float2(*(const __half2*)&hacc[mi][ni][h]);
                        const size_t ib = (size_t)mr * SC_DIM + n;
                        float2 iv = *(const float2*)(g_in + ib);
                        float v0, v1;
                        if (!css) {
                            v0 = TAUF * (c.x + bias_s[n])     + OMTF * iv.x;
                            v1 = TAUF * (c.y + bias_s[n + 1]) + OMTF * iv.y;
                        } else {
                            v0 = TAUF * (c.x + bias_css[n - S_DIM])     + OMTF * iv.x;
                            v1 = TAUF * (c.y + bias_css[n - S_DIM + 1]) + OMTF * iv.y;
                        }
                        *(float2*)(g_in + ib) = make_float2(v0, v1);
                        const float a0 = sigf(v0), a1 = sigf(v1);
                        *(__half2*)(Aout + ib) = __floats2half2_rn(a0, a1);
                        if (!css && dptr)
                            *(float2*)(dptr + (size_t)mr * S_DIM + n) = make_float2(a0, a1);
                    }
                }
            }
        }

        __syncthreads();
        if (tid == 0) red_release(&g_ready[t * R_TILES_M + m]);
    }
}

// ---------------- small helper kernels ----------------
__global__ void init_state() {
    int idx = blockIdx.x * blockDim.x + threadIdx.x;
    if (idx >= B_DIM * SC_DIM) return;
    g_in[idx] = 0.0f;
    g_act0[idx] = __float2half_rn(0.5f);
    if (idx < T_STEPS * R_TILES_M) g_ready[idx] = 0u;
    if (idx == 0) g_counter = 0u;
}

__global__ void prep_wph(const float* __restrict__ w) {
    int i = blockIdx.x * blockDim.x + threadIdx.x;
    if (i >= H_DIM * P_DIM) return;
    int n = i / P_DIM, k = i % P_DIM;
    g_wphT[i] = __float2half_rn(w[k * H_DIM + n]);
}

__global__ void prep_wcomb(const float* __restrict__ w_ss,
                           const float* __restrict__ w_sc,
                           const float* __restrict__ w_cs,
                           const float* __restrict__ w_hs) {
    int i = blockIdx.x * blockDim.x + threadIdx.x;
    if (i >= SC_DIM * KCAT) return;
    int n = i / KCAT, k = i % KCAT;
    float v = 0.0f;
    if (n < S_DIM) {
        if (k < S_DIM)        v = w_ss[k * S_DIM + n];
        else if (k < SC_DIM)  v = w_cs[(k - S_DIM) * S_DIM + n];
        else                  v = w_hs[(k - SC_DIM) * S_DIM + n];
    } else {
        if (k < S_DIM)        v = w_sc[k * C_DIM + (n - S_DIM)];
    }
    g_wcombT[i] = __float2half_rn(v);
}

// ---------------- host side ----------------
typedef CUresult (*PFN_tmapEncode)(
    CUtensorMap*, CUtensorMapDataType, cuuint32_t, void*,
    const cuuint64_t*, const cuuint64_t*, const cuuint32_t*, const cuuint32_t*,
    CUtensorMapInterleave, CUtensorMapSwizzle, CUtensorMapL2promotion,
    CUtensorMapFloatOOBfill);

static void make_map2d(PFN_tmapEncode fn, CUtensorMap* m, void* ptr,
                       uint64_t K, uint64_t M) {
    cuuint64_t dims[2]    = {K, M};
    cuuint64_t strides[1] = {K * 2};
    cuuint32_t box[2]     = {BK, BM};
    cuuint32_t es[2]      = {1, 1};
    fn(m, CU_TENSOR_MAP_DATA_TYPE_FLOAT16, 2, ptr, dims, strides, box, es,
       CU_TENSOR_MAP_INTERLEAVE_NONE, CU_TENSOR_MAP_SWIZZLE_128B,
       CU_TENSOR_MAP_L2_PROMOTION_L2_128B, CU_TENSOR_MAP_FLOAT_OOB_FILL_NONE);
}

extern "C" void kernel_launch(void* const* d_in, const int* in_sizes, int n_in,
                              void* d_out, int out_size)
{
    const float* x     = (const float*)d_in[0];
    const float* w_ph  = (const float*)d_in[1];
    const float* w_hs  = (const float*)d_in[2];
    const float* w_ss  = (const float*)d_in[3];
    const float* w_sc  = (const float*)d_in[4];
    const float* w_cs  = (const float*)d_in[5];
    const float* b_hps = (const float*)d_in[6];
    const float* b_s   = (const float*)d_in[7];
    const float* b_css = (const float*)d_in[8];
    float* out = (float*)d_out;

    void *zbuf, *wphT;
    cudaGetSymbolAddress(&zbuf, g_zbuf);
    cudaGetSymbolAddress(&wphT, g_wphT);

    PFN_tmapEncode encode = nullptr;
    cudaDriverEntryPointQueryResult qr;
    cudaGetDriverEntryPointByVersion("cuTensorMapEncodeTiled", (void**)&encode,
                                     12000, cudaEnableDefault, &qr);

    const uint64_t MB = (uint64_t)T_STEPS * B_DIM;

    CUtensorMap m_wph;
    make_map2d(encode, &m_wph, wphT, P_DIM, H_DIM);

    cudaFuncSetAttribute(gemm_x2,     cudaFuncAttributeMaxDynamicSharedMemorySize, SMEMX2_TOTAL);
    cudaFuncSetAttribute(rec_persist, cudaFuncAttributeMaxDynamicSharedMemorySize, SMEM_TOTAL);

    // 0) preps + state/flag init
    prep_wph<<<(H_DIM * P_DIM + 255) / 256, 256>>>(w_ph);
    prep_wcomb<<<(SC_DIM * KCAT + 255) / 256, 256>>>(w_ss, w_sc, w_cs, w_hs);
    init_state<<<(B_DIM * SC_DIM + 255) / 256, 256>>>();

    // 1) Z = X(fp32) @ WphT^T — A resident, n-loop, fp16 accum
    gemm_x2<<<(unsigned)(MB / BM), 256, SMEMX2_TOTAL>>>(x, m_wph, (__half*)zbuf);

    // 2) hps scan
    hps_scan<<<(B_DIM * H_DIM) / 256, 256>>>(b_hps);

    // 3) 20 recurrent steps, K-split warp pairs, persistent
    rec_persist<<<R_GRID, 256, SMEM_TOTAL>>>(b_s, b_css, out);
}

// round 16
// speedup vs baseline: 1.4046x; 1.4046x over previous
#include <cuda_runtime.h>
#include <cuda_fp16.h>
#include <cuda.h>
#include <math.h>
#include <stdint.h>

// ---------------- problem constants ----------------
#define T_STEPS 20
#define B_DIM   16384
#define P_DIM   256
#define H_DIM   512
#define S_DIM   512
#define C_DIM   128
#define SC_DIM  640
#define KCAT    1152
#define TAUF    0.25f
#define OMTF    0.75f

// ---------------- GEMM tile config ----------------
#define BM 128
#define BN 128
#define BK 64
#define NSTAGE 3
#define A_BYTES (BM * BK * 2)
#define B_BYTES (BN * BK * 2)
#define STAGE_BYTES (A_BYTES + B_BYTES)
#define SMEM_TOTAL (2048 + NSTAGE * STAGE_BYTES)   // 100352
#define OFF_FULL(s)  ((s) * 8)

// gemm_x2: A fully resident (4 chunks, 64KB) + 2-stage TMA B ring
#define SMEMX2_TOTAL (2048 + 4 * A_BYTES + 2 * B_BYTES)   // 100352

// recurrent persistent kernel
#define R_TILES_M   (B_DIM / BM)      // 128
#define R_TILES_N   (SC_DIM / BN)     // 5
#define R_TILES     (R_TILES_M * R_TILES_N)          // 640
#define R_TOTAL     (T_STEPS * R_TILES)              // 12800
#define R_GRID      296

// ---------------- device scratch ----------------
__device__ __align__(256) __half g_zbuf[(size_t)T_STEPS * B_DIM * H_DIM];
__device__ __align__(256) __half g_act0[(size_t)B_DIM * SC_DIM];
__device__ __align__(256) __half g_act1[(size_t)B_DIM * SC_DIM];
__device__ __align__(256) float  g_in  [(size_t)B_DIM * SC_DIM];
__device__ __align__(256) __half g_wphT  [H_DIM * P_DIM];
__device__ __align__(256) __half g_wcombT[SC_DIM * KCAT];
__device__ unsigned g_ready[T_STEPS * R_TILES_M];
__device__ unsigned g_counter;

// ---------------- PTX helpers ----------------
__device__ __forceinline__ uint32_t smem_u32(const void* p) {
    uint32_t a;
    asm("{ .reg .u64 t; cvta.to.shared.u64 t, %1; cvt.u32.u64 %0, t; }" : "=r"(a) : "l"(p));
    return a;
}
__device__ __forceinline__ void mbar_init(uint32_t m, uint32_t cnt) {
    asm volatile("mbarrier.init.shared.b64 [%0], %1;" :: "r"(m), "r"(cnt) : "memory");
}
__device__ __forceinline__ void mbar_expect_tx(uint32_t m, uint32_t bytes) {
    asm volatile("mbarrier.arrive.expect_tx.shared.b64 _, [%0], %1;" :: "r"(m), "r"(bytes) : "memory");
}
__device__ __forceinline__ void mbar_wait(uint32_t m, uint32_t parity) {
    asm volatile(
        "{\n\t.reg .pred P;\n\t"
        "WL_%=:\n\t"
        "mbarrier.try_wait.parity.acquire.cta.shared::cta.b64 P, [%0], %1, 0x989680;\n\t"
        "@P bra.uni WD_%=;\n\t"
        "bra.uni WL_%=;\n\t"
        "WD_%=:\n\t}"
        :: "r"(m), "r"(parity) : "memory");
}
__device__ __forceinline__ void tma2d(uint32_t dst, const CUtensorMap* map, int x, int y, uint32_t mbar) {
    asm volatile(
        "cp.async.bulk.tensor.2d.shared::cta.global.tile.mbarrier::complete_tx::bytes "
        "[%0], [%1, {%2, %3}], [%4];"
        :: "r"(dst), "l"(map), "r"(x), "r"(y), "r"(mbar) : "memory");
}
__device__ __forceinline__ void ldsm4(uint32_t* r, uint32_t addr) {
    asm volatile("ldmatrix.sync.aligned.m8n8.x4.shared.b16 {%0,%1,%2,%3}, [%4];"
                 : "=r"(r[0]), "=r"(r[1]), "=r"(r[2]), "=r"(r[3]) : "r"(addr));
}
__device__ __forceinline__ void mma16816h(uint32_t* c, const uint32_t* a, uint32_t b0, uint32_t b1) {
    asm volatile(
        "mma.sync.aligned.m16n8k16.row.col.f16.f16.f16.f16 "
        "{%0,%1}, {%2,%3,%4,%5}, {%6,%7}, {%0,%1};"
        : "+r"(c[0]), "+r"(c[1])
        : "r"(a[0]), "r"(a[1]), "r"(a[2]), "r"(a[3]), "r"(b0), "r"(b1));
}
__device__ __forceinline__ void cpa16(uint32_t dst, const void* src) {
    asm volatile("cp.async.cg.shared.global [%0], [%1], 16;" :: "r"(dst), "l"(src));
}
__device__ __forceinline__ void cpa_commit() { asm volatile("cp.async.commit_group;" ::: "memory"); }
template<int N> __device__ __forceinline__ void cpa_wait() {
    asm volatile("cp.async.wait_group %0;" :: "n"(N) : "memory");
}
__device__ __forceinline__ void red_release(unsigned* p) {
    asm volatile("red.release.gpu.global.add.u32 [%0], 1;" :: "l"(p) : "memory");
}
__device__ __forceinline__ unsigned ld_acquire(const unsigned* p) {
    unsigned v;
    asm volatile("ld.acquire.gpu.global.u32 %0, [%1];" : "=r"(v) : "l"(p) : "memory");
    return v;
}
__device__ __forceinline__ float sigf(float x) { return 1.0f / (1.0f + __expf(-x)); }

// ============================================================================
// gemm_x2: Z = X(fp32) @ WphT^T, fp16 accum (R12-validated, unchanged)
// ============================================================================
__global__ void __launch_bounds__(256, 2)
gemm_x2(const float* __restrict__ X,
        const __grid_constant__ CUtensorMap tma_b,
        __half* __restrict__ hout)
{
    extern __shared__ char smem[];
    const uint32_t sb = smem_u32(smem);
    const uint32_t stage0 = (sb + 64 + 1023) & ~1023u;
    const uint32_t A0 = stage0;
    const uint32_t B0 = stage0 + 4 * A_BYTES;
    const int tid  = threadIdx.x;
    const int lane = tid & 31;
    const int w    = tid >> 5;
    const int wm   = w & 3;
    const int wn   = w >> 2;
    const int m0 = blockIdx.x * BM;

    if (tid == 0) {
        mbar_init(sb + OFF_FULL(0), 1);
        mbar_init(sb + OFF_FULL(1), 1);
    }
    __syncthreads();
    if (tid == 0) {
        mbar_expect_tx(sb + OFF_FULL(0), B_BYTES);
        tma2d(B0,           &tma_b, 0 * BK, 0, sb + OFF_FULL(0));
        mbar_expect_tx(sb + OFF_FULL(1), B_BYTES);
        tma2d(B0 + B_BYTES, &tma_b, 1 * BK, 0, sb + OFF_FULL(1));
    }

    int rI[8], cI[8];
    uint32_t sOff[8];
    #pragma unroll
    for (int q = 0; q < 8; q++) {
        int i = tid + q * 256;
        int r = i >> 4, c4 = i & 15;
        int c0 = c4 * 4;
        rI[q] = r; cI[q] = c0;
        sOff[q] = (uint32_t)r * 128 + (uint32_t)((((c0 >> 3) ^ (r & 7)) * 16) + (c0 & 7) * 2);
    }
    #pragma unroll
    for (int c = 0; c < 4; c++) {
        float4 xv[8];
        #pragma unroll
        for (int q = 0; q < 8; q++)
            xv[q] = __ldg((const float4*)(X + (size_t)(m0 + rI[q]) * P_DIM + c * BK + cI[q]));
        const uint32_t stA = A0 + c * A_BYTES;
        #pragma unroll
        for (int q = 0; q < 8; q++) {
            uint32_t d = stA + sOff[q];
            __half2 h01 = __floats2half2_rn(xv[q].x, xv[q].y);
            __half2 h23 = __floats2half2_rn(xv[q].z, xv[q].w);
            asm volatile("st.shared.b32 [%0], %1;" :: "r"(d),     "r"(*(uint32_t*)&h01));
            asm volatile("st.shared.b32 [%0], %1;" :: "r"(d + 4), "r"(*(uint32_t*)&h23));
        }
    }
    __syncthreads();

    const uint32_t xr   = (uint32_t)(lane & 7) * 16;
    const uint32_t koff = (uint32_t)(lane >> 4) * 16;
    uint32_t aRow[2], bRow[4];
    #pragma unroll
    for (int mi = 0; mi < 2; mi++)
        aRow[mi] = (uint32_t)(wm * 32 + mi * 16 + (lane & 15)) * 128;
    #pragma unroll
    for (int nq = 0; nq < 4; nq++)
        bRow[nq] = (uint32_t)(wn * 64 + nq * 16 + (lane & 15)) * 128;
    const int rbase = lane >> 2;
    const int cpair = (lane & 3) * 2;

    #pragma unroll 1
    for (int nt = 0; nt < 4; nt++) {
        uint32_t hacc[2][8][2];
        #pragma unroll
        for (int mi = 0; mi < 2; mi++)
            #pragma unroll
            for (int ni = 0; ni < 8; ni++) { hacc[mi][ni][0] = 0u; hacc[mi][ni][1] = 0u; }

        #pragma unroll
        for (int kc = 0; kc < 4; kc++) {
            const int idx = nt * 4 + kc;
            mbar_wait(sb + OFF_FULL(idx & 1), (uint32_t)((idx >> 1) & 1));
            const uint32_t stA = A0 + kc * A_BYTES;
            const uint32_t stB = B0 + (idx & 1) * B_BYTES;
            #pragma unroll
            for (int k16 = 0; k16 < 4; k16++) {
                const uint32_t kb = (uint32_t)k16 * 32 + koff;
                uint32_t af[2][4], bf[4][4];
                #pragma unroll
                for (int mi = 0; mi < 2; mi++)
                    ldsm4(af[mi], stA + aRow[mi] + (kb ^ xr));
                #pragma unroll
                for (int nq = 0; nq < 4; nq++)
                    ldsm4(bf[nq], stB + bRow[nq] + (kb ^ xr));
                #pragma unroll
                for (int mi = 0; mi < 2; mi++)
                    #pragma unroll
                    for (int nq = 0; nq < 4; nq++) {
                        mma16816h(hacc[mi][nq * 2 + 0], af[mi], bf[nq][0], bf[nq][2]);
                        mma16816h(hacc[mi][nq * 2 + 1], af[mi], bf[nq][1], bf[nq][3]);
                    }
            }
            __syncthreads();
            if (tid == 0 && idx + 2 < 16) {
                const int i2 = idx + 2;
                const int nt2 = i2 >> 2, kc2 = i2 & 3;
                mbar_expect_tx(sb + OFF_FULL(i2 & 1), B_BYTES);
                tma2d(B0 + (i2 & 1) * B_BYTES, &tma_b, kc2 * BK, nt2 * BN, sb + OFF_FULL(i2 & 1));
            }
        }

        const int n0 = nt * BN;
        #pragma unroll
        for (int mi = 0; mi < 2; mi++)
            #pragma unroll
            for (int h = 0; h < 2; h++) {
                const int m = m0 + wm * 32 + mi * 16 + rbase + h * 8;
                #pragma unroll
                for (int ni = 0; ni < 8; ni++) {
                    const int n = n0 + wn * 64 + ni * 8 + cpair;
                    *(uint32_t*)(hout + (size_t)m * H_DIM + n) = hacc[mi][ni][h];
                }
            }
    }
}

// ============================================================================
// hps_scan: vectorized x4 (8B loads/stores), fully parallel
// ============================================================================
__global__ void hps_scan(const float* __restrict__ bias_hps) {
    int idx = blockIdx.x * blockDim.x + threadIdx.x;   // over B*H/4
    if (idx >= B_DIM * H_DIM / 4) return;
    const int h4 = (idx * 4) % H_DIM;
    float b0 = bias_hps[h4],     b1 = bias_hps[h4 + 1];
    float b2 = bias_hps[h4 + 2], b3 = bias_hps[h4 + 3];
    float p0 = 0.0f, p1 = 0.0f, p2 = 0.0f, p3 = 0.0f;
    __half2* base = (__half2*)g_zbuf + (size_t)idx * 2;
    #pragma unroll
    for (int t = 0; t < T_STEPS; t++) {
        __half2* p = base + (size_t)t * (B_DIM * H_DIM / 2);
        const __half2 zA = p[0], zB = p[1];
        const float2 za = __half22float2(zA), zb = __half22float2(zB);
        p[0] = __floats2half2_rn(sigf(p0), sigf(p1));
        p[1] = __floats2half2_rn(sigf(p2), sigf(p3));
        p0 = TAUF * (za.x + b0) + OMTF * p0;
        p1 = TAUF * (za.y + b1) + OMTF * p1;
        p2 = TAUF * (zb.x + b2) + OMTF * p2;
        p3 = TAUF * (zb.y + b3) + OMTF * p3;
    }
}

// ============================================================================
// rec_persist: R12 mainloop (proven) + loop-top sync guard + t=19 css skip
// + dead store elimination at t=19.
// ============================================================================
__global__ void __launch_bounds__(256, 2)
rec_persist(const float* __restrict__ bias_s,
            const float* __restrict__ bias_css,
            float* __restrict__ out)
{
    extern __shared__ char smem[];
    unsigned* sg = (unsigned*)smem;
    const uint32_t sb = smem_u32(smem);
    const uint32_t stage0 = (sb + 16 + 1023) & ~1023u;
    const int tid  = threadIdx.x;
    const int lane = tid & 31;
    const int w    = tid >> 5;
    const int wm   = w & 3;
    const int wn   = w >> 2;

    uint32_t dstOff[4];
    int rIdx[4], cIdx[4];
    #pragma unroll
    for (int p = 0; p < 4; p++) {
        int i = tid + p * 256;
        int r = i >> 3, c = i & 7;
        rIdx[p] = r; cIdx[p] = c;
        dstOff[p] = (uint32_t)r * 128 + (uint32_t)((c ^ (r & 7)) * 16);
    }

    const uint32_t xr   = (uint32_t)(lane & 7) * 16;
    const uint32_t koff = (uint32_t)(lane >> 4) * 16;
    uint32_t aRow[2], bRow[4];
    #pragma unroll
    for (int mi = 0; mi < 2; mi++)
        aRow[mi] = (uint32_t)(wm * 32 + mi * 16 + (lane & 15)) * 128;
    #pragma unroll
    for (int nq = 0; nq < 4; nq++)
        bRow[nq] = (uint32_t)(wn * 64 + nq * 16 + (lane & 15)) * 128;

    while (true) {
        __syncthreads();                 // guard sg[0] reuse (incl. continue path)
        if (tid == 0) sg[0] = atomicAdd(&g_counter, 1u);
        __syncthreads();
        const unsigned g = sg[0];
        if (g >= (unsigned)R_TOTAL) break;

        const int t  = (int)(g / R_TILES);
        const int rm = (int)(g % R_TILES);
        const int m  = rm / R_TILES_N;
        const int nn = rm % R_TILES_N;
        const int m0 = m * BM;
        const int n0 = nn * BN;
        const bool css = (n0 >= S_DIM);
        const bool last = (t == T_STEPS - 1);
        const int nk = css ? (S_DIM / BK) : (KCAT / BK);   // 8 or 18

        if (last && css) continue;       // dead tile: css state at t=19 never read

        if (t > 0) {
            if (tid == 0) {
                while (ld_acquire(&g_ready[(t - 1) * R_TILES_M + m]) < (unsigned)R_TILES_N)
                    __nanosleep(64);
            }
        }
        __syncthreads();

        const __half* Aact = (t & 1) ? g_act1 : g_act0;
        __half*       Aout = (t & 1) ? g_act0 : g_act1;
        const __half* Ahps = g_zbuf + (size_t)t * B_DIM * H_DIM;

        #define A_SRC(kc, p) \
            (((kc) < R_TILES_N * 2) \
             ? (Aact + (size_t)(m0 + rIdx[p]) * SC_DIM + (kc) * BK + cIdx[p] * 8) \
             : (Ahps + (size_t)(m0 + rIdx[p]) * H_DIM + ((kc) - R_TILES_N * 2) * BK + cIdx[p] * 8))
        #define PREFETCH(kc) do { \
            const uint32_t st_ = stage0 + ((kc) % NSTAGE) * STAGE_BYTES; \
            _Pragma("unroll") \
            for (int p = 0; p < 4; p++) \
                cpa16(st_ + dstOff[p], A_SRC((kc), p)); \
            _Pragma("unroll") \
            for (int p = 0; p < 4; p++) \
                cpa16(st_ + A_BYTES + dstOff[p], \
                      g_wcombT + (size_t)(n0 + rIdx[p]) * KCAT + (kc) * BK + cIdx[p] * 8); \
            cpa_commit(); \
        } while (0)

        PREFETCH(0);
        PREFETCH(1);
        PREFETCH(2);

        uint32_t hacc[2][8][2];
        #pragma unroll
        for (int mi = 0; mi < 2; mi++)
            #pragma unroll
            for (int ni = 0; ni < 8; ni++) { hacc[mi][ni][0] = 0u; hacc[mi][ni][1] = 0u; }

        #pragma unroll 1
        for (int kc = 0; kc < nk; kc++) {
            const int rem = nk - 1 - kc;
            if (rem >= 2)      cpa_wait<NSTAGE - 1>();
            else if (rem == 1) cpa_wait<1>();
            else               cpa_wait<0>();
            __syncthreads();

            const uint32_t stA = stage0 + (kc % NSTAGE) * STAGE_BYTES;
            const uint32_t stB = stA + A_BYTES;

            #pragma unroll
            for (int k16 = 0; k16 < 4; k16++) {
                const uint32_t kb = (uint32_t)k16 * 32 + koff;
                uint32_t af[2][4], bf[4][4];
                #pragma unroll
                for (int mi = 0; mi < 2; mi++)
                    ldsm4(af[mi], stA + aRow[mi] + (kb ^ xr));
                #pragma unroll
                for (int nq = 0; nq < 4; nq++)
                    ldsm4(bf[nq], stB + bRow[nq] + (kb ^ xr));
                #pragma unroll
                for (int mi = 0; mi < 2; mi++)
                    #pragma unroll
                    for (int nq = 0; nq < 4; nq++) {
                        mma16816h(hacc[mi][nq * 2 + 0], af[mi], bf[nq][0], bf[nq][2]);
                        mma16816h(hacc[mi][nq * 2 + 1], af[mi], bf[nq][1], bf[nq][3]);
                    }
            }
            __syncthreads();
            if (kc + NSTAGE < nk) PREFETCH(kc + NSTAGE);
        }
        #undef PREFETCH
        #undef A_SRC

        float* dptr = (t >= T_STEPS - 4)
                      ? out + (size_t)(t - (T_STEPS - 4)) * B_DIM * S_DIM
                      : nullptr;
        const int rbase = lane >> 2;
        const int cpair = (lane & 3) * 2;

        #pragma unroll
        for (int mi = 0; mi < 2; mi++) {
            #pragma unroll
            for (int h = 0; h < 2; h++) {
                const int mr = m0 + wm * 32 + mi * 16 + rbase + h * 8;
                #pragma unroll
                for (int ni = 0; ni < 8; ni++) {
                    const int n = n0 + wn * 64 + ni * 8 + cpair;
                    const float2 c = __half22float2(*(const __half2*)&hacc[mi][ni][h]);
                    const size_t ib = (size_t)mr * SC_DIM + n;
                    float2 iv = *(const float2*)(g_in + ib);
                    float v0, v1;
                    if (!css) {
                        v0 = TAUF * (c.x + bias_s[n])     + OMTF * iv.x;
                        v1 = TAUF * (c.y + bias_s[n + 1]) + OMTF * iv.y;
                    } else {
                        v0 = TAUF * (c.x + bias_css[n - S_DIM])     + OMTF * iv.x;
                        v1 = TAUF * (c.y + bias_css[n - S_DIM + 1]) + OMTF * iv.y;
                    }
                    const float a0 = sigf(v0), a1 = sigf(v1);
                    if (!last) {
                        *(float2*)(g_in + ib) = make_float2(v0, v1);
                        *(__half2*)(Aout + ib) = __floats2half2_rn(a0, a1);
                    }
                    if (!css && dptr)
                        *(float2*)(dptr + (size_t)mr * S_DIM + n) = make_float2(a0, a1);
                }
            }
        }

        if (!last) {
            __syncthreads();
            if (tid == 0) red_release(&g_ready[t * R_TILES_M + m]);
        }
    }
}

// ---------------- small helper kernels ----------------
__global__ void init_state() {
    int idx = blockIdx.x * blockDim.x + threadIdx.x;
    if (idx >= B_DIM * SC_DIM) return;
    g_in[idx] = 0.0f;
    g_act0[idx] = __float2half_rn(0.5f);
    if (idx < T_STEPS * R_TILES_M) g_ready[idx] = 0u;
    if (idx == 0) g_counter = 0u;
}

__global__ void prep_wph(const float* __restrict__ w) {
    int i = blockIdx.x * blockDim.x + threadIdx.x;
    if (i >= H_DIM * P_DIM) return;
    int n = i / P_DIM, k = i % P_DIM;
    g_wphT[i] = __float2half_rn(w[k * H_DIM + n]);
}

__global__ void prep_wcomb(const float* __restrict__ w_ss,
                           const float* __restrict__ w_sc,
                           const float* __restrict__ w_cs,
                           const float* __restrict__ w_hs) {
    int i = blockIdx.x * blockDim.x + threadIdx.x;
    if (i >= SC_DIM * KCAT) return;
    int n = i / KCAT, k = i % KCAT;
    float v = 0.0f;
    if (n < S_DIM) {
        if (k < S_DIM)        v = w_ss[k * S_DIM + n];
        else if (k < SC_DIM)  v = w_cs[(k - S_DIM) * S_DIM + n];
        else                  v = w_hs[(k - SC_DIM) * S_DIM + n];
    } else {
        if (k < S_DIM)        v = w_sc[k * C_DIM + (n - S_DIM)];
    }
    g_wcombT[i] = __float2half_rn(v);
}

// ---------------- host side ----------------
typedef CUresult (*PFN_tmapEncode)(
    CUtensorMap*, CUtensorMapDataType, cuuint32_t, void*,
    const cuuint64_t*, const cuuint64_t*, const cuuint32_t*, const cuuint32_t*,
    CUtensorMapInterleave, CUtensorMapSwizzle, CUtensorMapL2promotion,
    CUtensorMapFloatOOBfill);

static void make_map2d(PFN_tmapEncode fn, CUtensorMap* m, void* ptr,
                       uint64_t K, uint64_t M) {
    cuuint64_t dims[2]    = {K, M};
    cuuint64_t strides[1] = {K * 2};
    cuuint32_t box[2]     = {BK, BM};
    cuuint32_t es[2]      = {1, 1};
    fn(m, CU_TENSOR_MAP_DATA_TYPE_FLOAT16, 2, ptr, dims, strides, box, es,
       CU_TENSOR_MAP_INTERLEAVE_NONE, CU_TENSOR_MAP_SWIZZLE_128B,
       CU_TENSOR_MAP_L2_PROMOTION_L2_128B, CU_TENSOR_MAP_FLOAT_OOB_FILL_NONE);
}

extern "C" void kernel_launch(void* const* d_in, const int* in_sizes, int n_in,
                              void* d_out, int out_size)
{
    const float* x     = (const float*)d_in[0];
    const float* w_ph  = (const float*)d_in[1];
    const float* w_hs  = (const float*)d_in[2];
    const float* w_ss  = (const float*)d_in[3];
    const float* w_sc  = (const float*)d_in[4];
    const float* w_cs  = (const float*)d_in[5];
    const float* b_hps = (const float*)d_in[6];
    const float* b_s   = (const float*)d_in[7];
    const float* b_css = (const float*)d_in[8];
    float* out = (float*)d_out;

    void *zbuf, *wphT;
    cudaGetSymbolAddress(&zbuf, g_zbuf);
    cudaGetSymbolAddress(&wphT, g_wphT);

    PFN_tmapEncode encode = nullptr;
    cudaDriverEntryPointQueryResult qr;
    cudaGetDriverEntryPointByVersion("cuTensorMapEncodeTiled", (void**)&encode,
                                     12000, cudaEnableDefault, &qr);

    const uint64_t MB = (uint64_t)T_STEPS * B_DIM;

    CUtensorMap m_wph;
    make_map2d(encode, &m_wph, wphT, P_DIM, H_DIM);

    cudaFuncSetAttribute(gemm_x2,     cudaFuncAttributeMaxDynamicSharedMemorySize, SMEMX2_TOTAL);
    cudaFuncSetAttribute(rec_persist, cudaFuncAttributeMaxDynamicSharedMemorySize, SMEM_TOTAL);

    // 0) preps + state/flag init
    prep_wph<<<(H_DIM * P_DIM + 255) / 256, 256>>>(w_ph);
    prep_wcomb<<<(SC_DIM * KCAT + 255) / 256, 256>>>(w_ss, w_sc, w_cs, w_hs);
    init_state<<<(B_DIM * SC_DIM + 255) / 256, 256>>>();

    // 1) Z = X(fp32) @ WphT^T — A resident, n-loop, fp16 accum
    gemm_x2<<<(unsigned)(MB / BM), 256, SMEMX2_TOTAL>>>(x, m_wph, (__half*)zbuf);

    // 2) hps scan (vectorized x4)
    hps_scan<<<(B_DIM * H_DIM / 4 + 255) / 256, 256>>>(b_hps);

    // 3) 20 recurrent steps with fused U (K-concat), persistent
    rec_persist<<<R_GRID, 256, SMEM_TOTAL>>>(b_s, b_css, out);
}